// round 9
// baseline (speedup 1.0000x reference)
#include <cuda_runtime.h>
#include <cuda_bf16.h>

// ---------------- problem constants ----------------
#define N_NODES   100000
#define E_EDGES   600000
#define RELS      20
#define D         128
#define TILE_E    64
#define MAX_TILES (E_EDGES / TILE_E + RELS)   // 9395
#define HSTR      65                          // padded smem row stride (bank-conflict free)

// ---------------- device scratch (no runtime allocation allowed) ----------------
__device__ float g_h0[(size_t)N_NODES * D];       // 51.2 MB  layer-1 input (emb gathered by x)
__device__ float g_buf[(size_t)N_NODES * D];      // 51.2 MB  layer-1 output (relu applied on read)
__device__ float g_invc[(size_t)RELS * N_NODES];  // 8 MB     1/max(count,1) per (rel,dst)
__device__ int   g_cnt [(size_t)RELS * N_NODES];  // 8 MB
__device__ int   g_hist[RELS];
__device__ int   g_relStart[RELS + 1];
__device__ int   g_cursor[RELS];
__device__ int   g_perm[E_EDGES];
__device__ int   g_tileRel[MAX_TILES];
__device__ int   g_tileOff[MAX_TILES];
__device__ int   g_tileCnt[MAX_TILES];

// ---------------- preprocessing ----------------
__global__ void k_zero_counts() {
    int i = blockIdx.x * blockDim.x + threadIdx.x;
    if (i < RELS * N_NODES) g_cnt[i] = 0;
    if (i < RELS) g_hist[i] = 0;
}

__global__ void k_count(const int* __restrict__ etype, const int* __restrict__ dst) {
    __shared__ int sh[RELS];
    if (threadIdx.x < RELS) sh[threadIdx.x] = 0;
    __syncthreads();
    int e = blockIdx.x * blockDim.x + threadIdx.x;
    if (e < E_EDGES) {
        int r = etype[e];
        atomicAdd(&g_cnt[(size_t)r * N_NODES + dst[e]], 1);
        atomicAdd(&sh[r], 1);
    }
    __syncthreads();
    if (threadIdx.x < RELS) atomicAdd(&g_hist[threadIdx.x], sh[threadIdx.x]);
}

__global__ void k_inv() {
    int i = blockIdx.x * blockDim.x + threadIdx.x;
    if (i < RELS * N_NODES) {
        int c = g_cnt[i];
        g_invc[i] = 1.0f / (float)(c > 1 ? c : 1);
    }
}

__global__ void k_scan() {   // 1 thread
    int b = 0;
    for (int r = 0; r < RELS; r++) {
        g_relStart[r] = b;
        b += g_hist[r];
        g_cursor[r] = 0;
    }
    g_relStart[RELS] = b;
}

__global__ void k_scatter(const int* __restrict__ etype) {
    __shared__ int scur[RELS];
    __shared__ int sbase[RELS];
    if (threadIdx.x < RELS) scur[threadIdx.x] = 0;
    __syncthreads();
    int e = blockIdx.x * blockDim.x + threadIdx.x;
    int r = 0, lp = 0;
    bool ok = (e < E_EDGES);
    if (ok) {
        r = etype[e];
        lp = atomicAdd(&scur[r], 1);
    }
    __syncthreads();
    if (threadIdx.x < RELS)
        sbase[threadIdx.x] = atomicAdd(&g_cursor[threadIdx.x], scur[threadIdx.x]);
    __syncthreads();
    if (ok) g_perm[g_relStart[r] + sbase[r] + lp] = e;
}

__global__ void k_tiles() {  // 1 block, 256 threads
    __shared__ int base[RELS + 1];
    if (threadIdx.x == 0) {
        int b = 0;
        for (int r = 0; r < RELS; r++) {
            base[r] = b;
            int seg = g_relStart[r + 1] - g_relStart[r];
            b += (seg + TILE_E - 1) / TILE_E;
        }
        base[RELS] = b;
    }
    __syncthreads();
    int total = base[RELS];
    for (int t = threadIdx.x; t < MAX_TILES; t += blockDim.x) {
        if (t >= total) { g_tileCnt[t] = 0; continue; }
        int r = 0;
        while (t >= base[r + 1]) r++;
        int i = t - base[r];
        int off = g_relStart[r] + i * TILE_E;
        int cnt = g_relStart[r + 1] - off;
        if (cnt > TILE_E) cnt = TILE_E;
        g_tileRel[t] = r;
        g_tileOff[t] = off;
        g_tileCnt[t] = cnt;
    }
}

__global__ void k_gather_emb(const int* __restrict__ x, const float* __restrict__ emb) {
    int i = blockIdx.x * blockDim.x + threadIdx.x;
    if (i < N_NODES * D) {
        int node = i >> 7;
        int k = i & (D - 1);
        g_h0[i] = emb[(size_t)x[node] * D + k];
    }
}

// ---------------- root GEMM: out = (relu?)(h) @ W + b ----------------
// block: 256 threads, tile 64 rows x 128 cols, register tile 4x8 per thread.
__global__ void __launch_bounds__(256) k_root(const float* __restrict__ h,
                                              const float* __restrict__ Wg,
                                              const float* __restrict__ bias,
                                              float* __restrict__ out,
                                              int reluIn) {
    extern __shared__ float smem[];
    float* sW = smem;            // D*D
    float* sH = smem + D * D;    // D*HSTR (transposed: sH[k*HSTR + row])
    float* sB = sH + D * HSTR;   // D

    int rowBase = blockIdx.x * TILE_E;

    {
        const float4* w4 = (const float4*)Wg;
        float4* s4 = (float4*)sW;
        for (int i = threadIdx.x; i < D * D / 4; i += 256) s4[i] = w4[i];
        if (threadIdx.x < D) sB[threadIdx.x] = bias[threadIdx.x];
    }
    for (int i = threadIdx.x; i < TILE_E * D; i += 256) {
        int e = i >> 7, k = i & (D - 1);
        int row = rowBase + e;
        float v = 0.f;
        if (row < N_NODES) {
            v = h[(size_t)row * D + k];
            if (reluIn) v = fmaxf(v, 0.f);
        }
        sH[k * HSTR + e] = v;
    }
    __syncthreads();

    int ct = threadIdx.x & 15;
    int et = threadIdx.x >> 4;
    int c0 = ct * 8;

    float acc[4][8];
#pragma unroll
    for (int i = 0; i < 4; i++)
#pragma unroll
        for (int j = 0; j < 8; j++) acc[i][j] = 0.f;

#pragma unroll 4
    for (int k = 0; k < D; k++) {
        float hv[4];
#pragma unroll
        for (int i = 0; i < 4; i++) hv[i] = sH[k * HSTR + et * 4 + i];
        float4 wa = *(const float4*)&sW[k * D + c0];
        float4 wb = *(const float4*)&sW[k * D + c0 + 4];
        float w[8] = {wa.x, wa.y, wa.z, wa.w, wb.x, wb.y, wb.z, wb.w};
#pragma unroll
        for (int i = 0; i < 4; i++)
#pragma unroll
            for (int j = 0; j < 8; j++) acc[i][j] += hv[i] * w[j];
    }

#pragma unroll
    for (int i = 0; i < 4; i++) {
        int row = rowBase + et * 4 + i;
        if (row < N_NODES) {
            float* op = out + (size_t)row * D + c0;
#pragma unroll
            for (int j = 0; j < 8; j++) op[j] = acc[i][j] + sB[c0 + j];
        }
    }
}

// ---------------- edge kernel: out[dst] += ((relu?)(h[src]) @ W[rel]) * invc[rel,dst] ----------------
__global__ void __launch_bounds__(256) k_edge(const float* __restrict__ h,
                                              const float* __restrict__ Wall,
                                              const int* __restrict__ src,
                                              const int* __restrict__ dst,
                                              float* __restrict__ out,
                                              int reluIn) {
    extern __shared__ float smem[];
    float* sW = smem;            // D*D
    float* sH = smem + D * D;    // D*HSTR
    int*   sSrc = (int*)(sH + D * HSTR);
    int*   sDst = sSrc + TILE_E;
    float* sInv = (float*)(sDst + TILE_E);

    int t = blockIdx.x;
    int cnt = g_tileCnt[t];
    if (cnt == 0) return;
    int r = g_tileRel[t];
    int off = g_tileOff[t];

    {
        const float4* w4 = (const float4*)(Wall + (size_t)r * D * D);
        float4* s4 = (float4*)sW;
        for (int i = threadIdx.x; i < D * D / 4; i += 256) s4[i] = w4[i];
    }
    if (threadIdx.x < TILE_E) {
        int i = threadIdx.x;
        if (i < cnt) {
            int e = g_perm[off + i];
            sSrc[i] = src[e];
            int d = dst[e];
            sDst[i] = d;
            sInv[i] = g_invc[(size_t)r * N_NODES + d];
        } else {
            sSrc[i] = 0; sDst[i] = 0; sInv[i] = 0.f;
        }
    }
    __syncthreads();

    for (int i = threadIdx.x; i < TILE_E * D; i += 256) {
        int e = i >> 7, k = i & (D - 1);
        float v = 0.f;
        if (e < cnt) {
            v = h[(size_t)sSrc[e] * D + k];
            if (reluIn) v = fmaxf(v, 0.f);
        }
        sH[k * HSTR + e] = v;
    }
    __syncthreads();

    int ct = threadIdx.x & 15;
    int et = threadIdx.x >> 4;
    int c0 = ct * 8;

    float acc[4][8];
#pragma unroll
    for (int i = 0; i < 4; i++)
#pragma unroll
        for (int j = 0; j < 8; j++) acc[i][j] = 0.f;

#pragma unroll 4
    for (int k = 0; k < D; k++) {
        float hv[4];
#pragma unroll
        for (int i = 0; i < 4; i++) hv[i] = sH[k * HSTR + et * 4 + i];
        float4 wa = *(const float4*)&sW[k * D + c0];
        float4 wb = *(const float4*)&sW[k * D + c0 + 4];
        float w[8] = {wa.x, wa.y, wa.z, wa.w, wb.x, wb.y, wb.z, wb.w};
#pragma unroll
        for (int i = 0; i < 4; i++)
#pragma unroll
            for (int j = 0; j < 8; j++) acc[i][j] += hv[i] * w[j];
    }

#pragma unroll
    for (int i = 0; i < 4; i++) {
        int e = et * 4 + i;
        if (e < cnt) {
            float inv = sInv[e];
            float* op = out + (size_t)sDst[e] * D + c0;
#pragma unroll
            for (int j = 0; j < 8; j++) atomicAdd(op + j, acc[i][j] * inv);
        }
    }
}

// ---------------- launch ----------------
#define SMEM_EDGE ((D * D + D * HSTR) * 4 + TILE_E * 12)
#define SMEM_ROOT ((D * D + D * HSTR + D) * 4)

extern "C" void kernel_launch(void* const* d_in, const int* in_sizes, int n_in,
                              void* d_out, int out_size) {
    const int*   x     = (const int*)d_in[0];
    const int*   edge  = (const int*)d_in[1];   // [2,E] row-major: src then dst
    const int*   etype = (const int*)d_in[2];
    const float* emb   = (const float*)d_in[3];
    const float* w1    = (const float*)d_in[4];
    const float* root1 = (const float*)d_in[5];
    const float* b1    = (const float*)d_in[6];
    const float* w2    = (const float*)d_in[7];
    const float* root2 = (const float*)d_in[8];
    const float* b2    = (const float*)d_in[9];
    float* out = (float*)d_out;

    const int* src = edge;
    const int* dstp = edge + E_EDGES;

    cudaFuncSetAttribute(k_edge, cudaFuncAttributeMaxDynamicSharedMemorySize, SMEM_EDGE);
    cudaFuncSetAttribute(k_root, cudaFuncAttributeMaxDynamicSharedMemorySize, SMEM_ROOT);

    float *h0, *buf;
    {
        void* p;
        cudaGetSymbolAddress(&p, g_h0);  h0 = (float*)p;
        cudaGetSymbolAddress(&p, g_buf); buf = (float*)p;
    }

    // ---- preprocessing (counts, inverse degrees, relation-sorted edge list, tile table)
    k_zero_counts<<<(RELS * N_NODES + 255) / 256, 256>>>();
    k_count<<<(E_EDGES + 255) / 256, 256>>>(etype, dstp);
    k_inv<<<(RELS * N_NODES + 255) / 256, 256>>>();
    k_scan<<<1, 1>>>();
    k_scatter<<<(E_EDGES + 255) / 256, 256>>>(etype);
    k_tiles<<<1, 256>>>();
    k_gather_emb<<<(N_NODES * D + 255) / 256, 256>>>(x, emb);

    const int rootGrid = (N_NODES + TILE_E - 1) / TILE_E;

    // ---- layer 1: buf = h0@root1 + b1 ; buf += per-edge messages
    k_root<<<rootGrid, 256, SMEM_ROOT>>>(h0, root1, b1, buf, 0);
    k_edge<<<MAX_TILES, 256, SMEM_EDGE>>>(h0, w1, src, dstp, buf, 0);

    // ---- layer 2: relu fused into reads of buf; output to d_out
    k_root<<<rootGrid, 256, SMEM_ROOT>>>(buf, root2, b2, out, 1);
    k_edge<<<MAX_TILES, 256, SMEM_EDGE>>>(buf, w2, src, dstp, out, 1);
}

// round 10
// speedup vs baseline: 2.5700x; 2.5700x over previous
#include <cuda_runtime.h>
#include <cuda_bf16.h>
#include <cstdint>

// ---------------- problem constants ----------------
#define N_NODES   100000
#define E_EDGES   600000
#define RELS      20
#define D         128
#define TILE_E    128
#define MAX_TILES ((E_EDGES + TILE_E - 1) / TILE_E + RELS)   // 4708
#define ROOT_TILES ((N_NODES + TILE_E - 1) / TILE_E)          // 782

// smem word layout (uint32 words), stride 68 words per row (136 bf16)
#define A_WORDS   (128 * 68)         // 8704
#define SM_AHI    0
#define SM_ALO    8704
#define SM_WHI    17408
#define SM_WLO    26112
#define SM_DST    34816
#define SM_INV    34944
#define SM_BIAS   35072
#define SM_SRC    35200
#define SMEM_WORDS 35328
#define SMEM_BYTES (SMEM_WORDS * 4)  // 141312

// ---------------- device scratch (no runtime allocation allowed) ----------------
__device__ float g_h0[(size_t)N_NODES * D];       // layer-1 input (emb gathered by x)
__device__ float g_buf[(size_t)N_NODES * D];      // layer-1 output
__device__ float g_invc[(size_t)RELS * N_NODES];  // 1/max(count,1) per (rel,dst)
__device__ int   g_cnt [(size_t)RELS * N_NODES];
__device__ int   g_hist[RELS];
__device__ int   g_relStart[RELS + 1];
__device__ int   g_cursor[RELS];
__device__ int   g_perm[E_EDGES];
__device__ int   g_tileRel[MAX_TILES];
__device__ int   g_tileOff[MAX_TILES];
__device__ int   g_tileCnt[MAX_TILES];

// split-bf16 weights, transposed to [n][k] for col-major B fragments
__device__ __nv_bfloat16 g_w1hi[(size_t)RELS * D * D];
__device__ __nv_bfloat16 g_w1lo[(size_t)RELS * D * D];
__device__ __nv_bfloat16 g_w2hi[(size_t)RELS * D * D];
__device__ __nv_bfloat16 g_w2lo[(size_t)RELS * D * D];
__device__ __nv_bfloat16 g_r1hi[D * D];
__device__ __nv_bfloat16 g_r1lo[D * D];
__device__ __nv_bfloat16 g_r2hi[D * D];
__device__ __nv_bfloat16 g_r2lo[D * D];

// ---------------- preprocessing ----------------
__global__ void k_zero_counts() {
    int i = blockIdx.x * blockDim.x + threadIdx.x;
    if (i < RELS * N_NODES) g_cnt[i] = 0;
    if (i < RELS) g_hist[i] = 0;
}

__global__ void k_count(const int* __restrict__ etype, const int* __restrict__ dst) {
    __shared__ int sh[RELS];
    if (threadIdx.x < RELS) sh[threadIdx.x] = 0;
    __syncthreads();
    int e = blockIdx.x * blockDim.x + threadIdx.x;
    if (e < E_EDGES) {
        int r = etype[e];
        atomicAdd(&g_cnt[(size_t)r * N_NODES + dst[e]], 1);
        atomicAdd(&sh[r], 1);
    }
    __syncthreads();
    if (threadIdx.x < RELS) atomicAdd(&g_hist[threadIdx.x], sh[threadIdx.x]);
}

__global__ void k_inv() {
    int i = blockIdx.x * blockDim.x + threadIdx.x;
    if (i < RELS * N_NODES) {
        int c = g_cnt[i];
        g_invc[i] = 1.0f / (float)(c > 1 ? c : 1);
    }
}

__global__ void k_scan() {   // 1 thread
    int b = 0;
    for (int r = 0; r < RELS; r++) {
        g_relStart[r] = b;
        b += g_hist[r];
        g_cursor[r] = 0;
    }
    g_relStart[RELS] = b;
}

__global__ void k_scatter(const int* __restrict__ etype) {
    __shared__ int scur[RELS];
    __shared__ int sbase[RELS];
    if (threadIdx.x < RELS) scur[threadIdx.x] = 0;
    __syncthreads();
    int e = blockIdx.x * blockDim.x + threadIdx.x;
    int r = 0, lp = 0;
    bool ok = (e < E_EDGES);
    if (ok) {
        r = etype[e];
        lp = atomicAdd(&scur[r], 1);
    }
    __syncthreads();
    if (threadIdx.x < RELS)
        sbase[threadIdx.x] = atomicAdd(&g_cursor[threadIdx.x], scur[threadIdx.x]);
    __syncthreads();
    if (ok) g_perm[g_relStart[r] + sbase[r] + lp] = e;
}

__global__ void k_tiles() {  // 1 block, 256 threads
    __shared__ int base[RELS + 1];
    if (threadIdx.x == 0) {
        int b = 0;
        for (int r = 0; r < RELS; r++) {
            base[r] = b;
            int seg = g_relStart[r + 1] - g_relStart[r];
            b += (seg + TILE_E - 1) / TILE_E;
        }
        base[RELS] = b;
    }
    __syncthreads();
    int total = base[RELS];
    for (int t = threadIdx.x; t < MAX_TILES; t += blockDim.x) {
        if (t >= total) { g_tileCnt[t] = 0; continue; }
        int r = 0;
        while (t >= base[r + 1]) r++;
        int i = t - base[r];
        int off = g_relStart[r] + i * TILE_E;
        int cnt = g_relStart[r + 1] - off;
        if (cnt > TILE_E) cnt = TILE_E;
        g_tileRel[t] = r;
        g_tileOff[t] = off;
        g_tileCnt[t] = cnt;
    }
}

__global__ void k_gather_emb(const int* __restrict__ x, const float* __restrict__ emb) {
    int i = blockIdx.x * blockDim.x + threadIdx.x;
    if (i < N_NODES * D) {
        int node = i >> 7;
        int k = i & (D - 1);
        g_h0[i] = emb[(size_t)x[node] * D + k];
    }
}

// W split + transpose: w[m][k][n] fp32 -> hi/lo[m][n][k] bf16
__global__ void k_wsplit(const float* __restrict__ w, __nv_bfloat16* __restrict__ hi,
                         __nv_bfloat16* __restrict__ lo, int total) {
    int idx = blockIdx.x * blockDim.x + threadIdx.x;
    if (idx >= total) return;
    int m = idx >> 14;
    int rem = idx & 16383;
    int k = rem >> 7;
    int n = rem & 127;
    float v = w[(size_t)m * 16384 + k * 128 + n];
    __nv_bfloat16 h = __float2bfloat16_rn(v);
    float res = v - __bfloat162float(h);
    __nv_bfloat16 l = __float2bfloat16_rn(res);
    size_t dst = (size_t)m * 16384 + n * 128 + k;
    hi[dst] = h;
    lo[dst] = l;
}

// ---------------- mma helpers ----------------
__device__ __forceinline__ void mma16816(float* c, uint32_t a0, uint32_t a1,
                                         uint32_t a2, uint32_t a3,
                                         uint32_t b0, uint32_t b1) {
    asm volatile(
        "mma.sync.aligned.m16n8k16.row.col.f32.bf16.bf16.f32 "
        "{%0,%1,%2,%3}, {%4,%5,%6,%7}, {%8,%9}, {%0,%1,%2,%3};"
        : "+f"(c[0]), "+f"(c[1]), "+f"(c[2]), "+f"(c[3])
        : "r"(a0), "r"(a1), "r"(a2), "r"(a3), "r"(b0), "r"(b1));
}

__device__ __forceinline__ uint32_t pack_bf2(__nv_bfloat16 a, __nv_bfloat16 b) {
    __nv_bfloat162 t;
    t.x = a; t.y = b;
    return *reinterpret_cast<uint32_t*>(&t);
}

// ---------------- fused GEMM kernel ----------------
// ROOTMODE=1: out[rowBase+e] = (relu?)h[rowBase+e] @ W + bias   (plain store)
// ROOTMODE=0: out[dst[e]]   += ((relu?)h[src[e]] @ W[rel]) * invc[rel,dst]   (atomics)
template<int ROOTMODE, int RELU>
__global__ void __launch_bounds__(512, 1)
k_mma(const float* __restrict__ h,
      const __nv_bfloat16* __restrict__ Whi,
      const __nv_bfloat16* __restrict__ Wlo,
      const float* __restrict__ bias,
      const int* __restrict__ src,
      const int* __restrict__ dst,
      float* __restrict__ out) {
    extern __shared__ uint32_t sm[];
    uint32_t* sAhi = sm + SM_AHI;
    uint32_t* sAlo = sm + SM_ALO;
    uint32_t* sWhi = sm + SM_WHI;
    uint32_t* sWlo = sm + SM_WLO;
    int*   sDst  = (int*)(sm + SM_DST);
    float* sInv  = (float*)(sm + SM_INV);
    float* sBias = (float*)(sm + SM_BIAS);
    int*   sSrc  = (int*)(sm + SM_SRC);

    int t = blockIdx.x;
    int cnt, r = 0, off = 0, rowBase = 0;
    if (ROOTMODE) {
        rowBase = t * TILE_E;
        cnt = N_NODES - rowBase;
        if (cnt > TILE_E) cnt = TILE_E;
    } else {
        cnt = g_tileCnt[t];
        if (cnt == 0) return;
        r = g_tileRel[t];
        off = g_tileOff[t];
    }

    const __nv_bfloat16* gwh = Whi + (size_t)r * (D * D);
    const __nv_bfloat16* gwl = Wlo + (size_t)r * (D * D);

    // ---- W staging (hi+lo), [n][k] rows of 128 bf16 -> smem stride 68 words
    for (int i = threadIdx.x; i < 128 * 16; i += 512) {
        int n = i >> 4, q = i & 15;
        *(uint4*)&sWhi[n * 68 + q * 4] = *(const uint4*)(gwh + n * 128 + q * 8);
        *(uint4*)&sWlo[n * 68 + q * 4] = *(const uint4*)(gwl + n * 128 + q * 8);
    }
    // ---- indices / bias
    if (threadIdx.x < TILE_E) {
        int i = threadIdx.x;
        if (ROOTMODE) {
            sBias[i] = bias[i];
        } else {
            if (i < cnt) {
                int e = g_perm[off + i];
                sSrc[i] = src[e];
                int d = dst[e];
                sDst[i] = d;
                sInv[i] = g_invc[(size_t)r * N_NODES + d];
            } else {
                sSrc[i] = 0; sDst[i] = 0; sInv[i] = 0.f;
            }
        }
    }
    __syncthreads();

    // ---- A staging: gather rows, relu, split to bf16 hi/lo
    for (int i = threadIdx.x; i < 128 * 32; i += 512) {
        int e = i >> 5, q = i & 31;
        float4 v = make_float4(0.f, 0.f, 0.f, 0.f);
        if (e < cnt) {
            const float* hp = ROOTMODE ? (h + (size_t)(rowBase + e) * D)
                                       : (h + (size_t)sSrc[e] * D);
            v = *(const float4*)(hp + q * 4);
            if (RELU) {
                v.x = fmaxf(v.x, 0.f); v.y = fmaxf(v.y, 0.f);
                v.z = fmaxf(v.z, 0.f); v.w = fmaxf(v.w, 0.f);
            }
        }
        __nv_bfloat16 h0 = __float2bfloat16_rn(v.x), h1 = __float2bfloat16_rn(v.y);
        __nv_bfloat16 h2 = __float2bfloat16_rn(v.z), h3 = __float2bfloat16_rn(v.w);
        __nv_bfloat16 l0 = __float2bfloat16_rn(v.x - __bfloat162float(h0));
        __nv_bfloat16 l1 = __float2bfloat16_rn(v.y - __bfloat162float(h1));
        __nv_bfloat16 l2 = __float2bfloat16_rn(v.z - __bfloat162float(h2));
        __nv_bfloat16 l3 = __float2bfloat16_rn(v.w - __bfloat162float(h3));
        int base = e * 68 + q * 2;
        uint2 hw, lw;
        hw.x = pack_bf2(h0, h1); hw.y = pack_bf2(h2, h3);
        lw.x = pack_bf2(l0, l1); lw.y = pack_bf2(l2, l3);
        *(uint2*)&sAhi[base] = hw;
        *(uint2*)&sAlo[base] = lw;
    }
    __syncthreads();

    // ---- MMA phase: 16 warps = 8 m-tiles (16 rows) x 2 n-halves (64 cols)
    int lane = threadIdx.x & 31;
    int wid  = threadIdx.x >> 5;
    int g    = lane >> 2;     // 0..7
    int tig  = lane & 3;      // 0..3
    int mtile = wid & 7;
    int nhalf = wid >> 3;
    int m0 = mtile * 16;

    float acc[8][4];
#pragma unroll
    for (int j = 0; j < 8; j++)
#pragma unroll
        for (int c = 0; c < 4; c++) acc[j][c] = 0.f;

    int aBase = (m0 + g) * 68 + tig;
    int bBase = (nhalf * 64 + g) * 68 + tig;

#pragma unroll
    for (int kc = 0; kc < 8; kc++) {
        int ko = kc * 8;
        uint32_t ah0 = sAhi[aBase + ko];
        uint32_t ah1 = sAhi[aBase + 544 + ko];
        uint32_t ah2 = sAhi[aBase + ko + 4];
        uint32_t ah3 = sAhi[aBase + 544 + ko + 4];
        uint32_t al0 = sAlo[aBase + ko];
        uint32_t al1 = sAlo[aBase + 544 + ko];
        uint32_t al2 = sAlo[aBase + ko + 4];
        uint32_t al3 = sAlo[aBase + 544 + ko + 4];
#pragma unroll
        for (int j = 0; j < 8; j++) {
            int bo = bBase + j * 544 + ko;
            uint32_t bh0 = sWhi[bo], bh1 = sWhi[bo + 4];
            uint32_t bl0 = sWlo[bo], bl1 = sWlo[bo + 4];
            mma16816(acc[j], al0, al1, al2, al3, bh0, bh1);  // lo*hi
            mma16816(acc[j], ah0, ah1, ah2, ah3, bl0, bl1);  // hi*lo
            mma16816(acc[j], ah0, ah1, ah2, ah3, bh0, bh1);  // hi*hi
        }
    }

    // ---- epilogue
    int colb = nhalf * 64 + tig * 2;
    int lr0 = m0 + g, lr1 = lr0 + 8;
    if (ROOTMODE) {
        int row0 = rowBase + lr0;
        if (row0 < N_NODES) {
            float* op = out + (size_t)row0 * D + colb;
#pragma unroll
            for (int j = 0; j < 8; j++) {
                float2 st;
                st.x = acc[j][0] + sBias[colb + j * 8];
                st.y = acc[j][1] + sBias[colb + j * 8 + 1];
                *(float2*)(op + j * 8) = st;
            }
        }
        int row1 = rowBase + lr1;
        if (row1 < N_NODES) {
            float* op = out + (size_t)row1 * D + colb;
#pragma unroll
            for (int j = 0; j < 8; j++) {
                float2 st;
                st.x = acc[j][2] + sBias[colb + j * 8];
                st.y = acc[j][3] + sBias[colb + j * 8 + 1];
                *(float2*)(op + j * 8) = st;
            }
        }
    } else {
        if (lr0 < cnt) {
            float inv = sInv[lr0];
            float* op = out + (size_t)sDst[lr0] * D + colb;
#pragma unroll
            for (int j = 0; j < 8; j++) {
                atomicAdd(op + j * 8,     acc[j][0] * inv);
                atomicAdd(op + j * 8 + 1, acc[j][1] * inv);
            }
        }
        if (lr1 < cnt) {
            float inv = sInv[lr1];
            float* op = out + (size_t)sDst[lr1] * D + colb;
#pragma unroll
            for (int j = 0; j < 8; j++) {
                atomicAdd(op + j * 8,     acc[j][2] * inv);
                atomicAdd(op + j * 8 + 1, acc[j][3] * inv);
            }
        }
    }
}

// ---------------- launch ----------------
extern "C" void kernel_launch(void* const* d_in, const int* in_sizes, int n_in,
                              void* d_out, int out_size) {
    const int*   x     = (const int*)d_in[0];
    const int*   edge  = (const int*)d_in[1];   // [2,E]: src row then dst row
    const int*   etype = (const int*)d_in[2];
    const float* emb   = (const float*)d_in[3];
    const float* w1    = (const float*)d_in[4];
    const float* root1 = (const float*)d_in[5];
    const float* b1    = (const float*)d_in[6];
    const float* w2    = (const float*)d_in[7];
    const float* root2 = (const float*)d_in[8];
    const float* b2    = (const float*)d_in[9];
    float* out = (float*)d_out;

    const int* src  = edge;
    const int* dstp = edge + E_EDGES;

    cudaFuncSetAttribute(k_mma<0, 0>, cudaFuncAttributeMaxDynamicSharedMemorySize, SMEM_BYTES);
    cudaFuncSetAttribute(k_mma<0, 1>, cudaFuncAttributeMaxDynamicSharedMemorySize, SMEM_BYTES);
    cudaFuncSetAttribute(k_mma<1, 0>, cudaFuncAttributeMaxDynamicSharedMemorySize, SMEM_BYTES);
    cudaFuncSetAttribute(k_mma<1, 1>, cudaFuncAttributeMaxDynamicSharedMemorySize, SMEM_BYTES);

    float *h0, *buf;
    __nv_bfloat16 *w1hi, *w1lo, *w2hi, *w2lo, *r1hi, *r1lo, *r2hi, *r2lo;
    {
        void* p;
        cudaGetSymbolAddress(&p, g_h0);   h0   = (float*)p;
        cudaGetSymbolAddress(&p, g_buf);  buf  = (float*)p;
        cudaGetSymbolAddress(&p, g_w1hi); w1hi = (__nv_bfloat16*)p;
        cudaGetSymbolAddress(&p, g_w1lo); w1lo = (__nv_bfloat16*)p;
        cudaGetSymbolAddress(&p, g_w2hi); w2hi = (__nv_bfloat16*)p;
        cudaGetSymbolAddress(&p, g_w2lo); w2lo = (__nv_bfloat16*)p;
        cudaGetSymbolAddress(&p, g_r1hi); r1hi = (__nv_bfloat16*)p;
        cudaGetSymbolAddress(&p, g_r1lo); r1lo = (__nv_bfloat16*)p;
        cudaGetSymbolAddress(&p, g_r2hi); r2hi = (__nv_bfloat16*)p;
        cudaGetSymbolAddress(&p, g_r2lo); r2lo = (__nv_bfloat16*)p;
    }

    // ---- preprocessing
    k_zero_counts<<<(RELS * N_NODES + 255) / 256, 256>>>();
    k_count<<<(E_EDGES + 255) / 256, 256>>>(etype, dstp);
    k_inv<<<(RELS * N_NODES + 255) / 256, 256>>>();
    k_scan<<<1, 1>>>();
    k_scatter<<<(E_EDGES + 255) / 256, 256>>>(etype);
    k_tiles<<<1, 256>>>();
    k_gather_emb<<<(N_NODES * D + 255) / 256, 256>>>(x, emb);

    // ---- weight split + transpose (bf16 hi/lo, [n][k])
    int wt = RELS * D * D;
    k_wsplit<<<(wt + 255) / 256, 256>>>(w1, w1hi, w1lo, wt);
    k_wsplit<<<(wt + 255) / 256, 256>>>(w2, w2hi, w2lo, wt);
    k_wsplit<<<(D * D + 255) / 256, 256>>>(root1, r1hi, r1lo, D * D);
    k_wsplit<<<(D * D + 255) / 256, 256>>>(root2, r2hi, r2lo, D * D);

    // ---- layer 1: buf = h0@root1 + b1 ; buf += edge messages
    k_mma<1, 0><<<ROOT_TILES, 512, SMEM_BYTES>>>(h0, r1hi, r1lo, b1, src, dstp, buf);
    k_mma<0, 0><<<MAX_TILES, 512, SMEM_BYTES>>>(h0, w1hi, w1lo, b1, src, dstp, buf);

    // ---- layer 2: relu fused into reads of buf
    k_mma<1, 1><<<ROOT_TILES, 512, SMEM_BYTES>>>(buf, r2hi, r2lo, b2, src, dstp, out);
    k_mma<0, 1><<<MAX_TILES, 512, SMEM_BYTES>>>(buf, w2hi, w2lo, b2, src, dstp, out);
}

// round 11
// speedup vs baseline: 2.6342x; 1.0250x over previous
#include <cuda_runtime.h>
#include <cuda_bf16.h>
#include <cstdint>

// ---------------- problem constants ----------------
#define N_NODES   100000
#define E_EDGES   600000
#define RELS      20
#define D         128
#define TILE_E    128
#define MAX_TILES ((E_EDGES + TILE_E - 1) / TILE_E + RELS)   // 4708
#define ROOT_TILES ((N_NODES + TILE_E - 1) / TILE_E)          // 782

// smem word layout (uint32 words), stride 68 words per row (136 bf16)
#define A_WORDS   (128 * 68)         // 8704
#define SM_AHI    0
#define SM_ALO    8704
#define SM_WHI    17408
#define SM_WLO    26112
#define SM_DST    34816
#define SM_INV    34944
#define SM_BIAS   35072
#define SM_SRC    35200
#define SMEM_WORDS 35328
#define SMEM_BYTES (SMEM_WORDS * 4)  // 141312
// output bounce tile: 128 rows x stride 132 fp32 = 16896 words, reuses [SM_AHI..SM_WHI)
#define OSTR      132

// ---------------- device scratch (no runtime allocation allowed) ----------------
__device__ float g_h0[(size_t)N_NODES * D];
__device__ float g_buf[(size_t)N_NODES * D];
__device__ float g_invc[(size_t)RELS * N_NODES];
__device__ int   g_cnt [(size_t)RELS * N_NODES];
__device__ int   g_hist[RELS];
__device__ int   g_relStart[RELS + 1];
__device__ int   g_cursor[RELS];
__device__ int   g_perm[E_EDGES];
__device__ int   g_tileRel[MAX_TILES];
__device__ int   g_tileOff[MAX_TILES];
__device__ int   g_tileCnt[MAX_TILES];

// split-bf16 weights, transposed to [n][k] for col-major B fragments
__device__ __nv_bfloat16 g_w1hi[(size_t)RELS * D * D];
__device__ __nv_bfloat16 g_w1lo[(size_t)RELS * D * D];
__device__ __nv_bfloat16 g_w2hi[(size_t)RELS * D * D];
__device__ __nv_bfloat16 g_w2lo[(size_t)RELS * D * D];
__device__ __nv_bfloat16 g_r1hi[D * D];
__device__ __nv_bfloat16 g_r1lo[D * D];
__device__ __nv_bfloat16 g_r2hi[D * D];
__device__ __nv_bfloat16 g_r2lo[D * D];

// ---------------- preprocessing ----------------
__global__ void k_zero_counts() {
    int i = blockIdx.x * blockDim.x + threadIdx.x;
    if (i < RELS * N_NODES) g_cnt[i] = 0;
    if (i < RELS) g_hist[i] = 0;
}

__global__ void k_count(const int* __restrict__ etype, const int* __restrict__ dst) {
    __shared__ int sh[RELS];
    if (threadIdx.x < RELS) sh[threadIdx.x] = 0;
    __syncthreads();
    int e = blockIdx.x * blockDim.x + threadIdx.x;
    if (e < E_EDGES) {
        int r = etype[e];
        atomicAdd(&g_cnt[(size_t)r * N_NODES + dst[e]], 1);
        atomicAdd(&sh[r], 1);
    }
    __syncthreads();
    if (threadIdx.x < RELS) atomicAdd(&g_hist[threadIdx.x], sh[threadIdx.x]);
}

__global__ void k_inv() {
    int i = blockIdx.x * blockDim.x + threadIdx.x;
    if (i < RELS * N_NODES) {
        int c = g_cnt[i];
        g_invc[i] = 1.0f / (float)(c > 1 ? c : 1);
    }
}

__global__ void k_scan() {   // 1 thread
    int b = 0;
    for (int r = 0; r < RELS; r++) {
        g_relStart[r] = b;
        b += g_hist[r];
        g_cursor[r] = 0;
    }
    g_relStart[RELS] = b;
}

__global__ void k_scatter(const int* __restrict__ etype) {
    __shared__ int scur[RELS];
    __shared__ int sbase[RELS];
    if (threadIdx.x < RELS) scur[threadIdx.x] = 0;
    __syncthreads();
    int e = blockIdx.x * blockDim.x + threadIdx.x;
    int r = 0, lp = 0;
    bool ok = (e < E_EDGES);
    if (ok) {
        r = etype[e];
        lp = atomicAdd(&scur[r], 1);
    }
    __syncthreads();
    if (threadIdx.x < RELS)
        sbase[threadIdx.x] = atomicAdd(&g_cursor[threadIdx.x], scur[threadIdx.x]);
    __syncthreads();
    if (ok) g_perm[g_relStart[r] + sbase[r] + lp] = e;
}

__global__ void k_tiles() {  // 1 block, 256 threads
    __shared__ int base[RELS + 1];
    if (threadIdx.x == 0) {
        int b = 0;
        for (int r = 0; r < RELS; r++) {
            base[r] = b;
            int seg = g_relStart[r + 1] - g_relStart[r];
            b += (seg + TILE_E - 1) / TILE_E;
        }
        base[RELS] = b;
    }
    __syncthreads();
    int total = base[RELS];
    for (int t = threadIdx.x; t < MAX_TILES; t += blockDim.x) {
        if (t >= total) { g_tileCnt[t] = 0; continue; }
        int r = 0;
        while (t >= base[r + 1]) r++;
        int i = t - base[r];
        int off = g_relStart[r] + i * TILE_E;
        int cnt = g_relStart[r + 1] - off;
        if (cnt > TILE_E) cnt = TILE_E;
        g_tileRel[t] = r;
        g_tileOff[t] = off;
        g_tileCnt[t] = cnt;
    }
}

__global__ void k_gather_emb(const int* __restrict__ x, const float* __restrict__ emb) {
    int i = blockIdx.x * blockDim.x + threadIdx.x;
    if (i < N_NODES * D) {
        int node = i >> 7;
        int k = i & (D - 1);
        g_h0[i] = emb[(size_t)x[node] * D + k];
    }
}

// W split + transpose: w[m][k][n] fp32 -> hi/lo[m][n][k] bf16
__global__ void k_wsplit(const float* __restrict__ w, __nv_bfloat16* __restrict__ hi,
                         __nv_bfloat16* __restrict__ lo, int total) {
    int idx = blockIdx.x * blockDim.x + threadIdx.x;
    if (idx >= total) return;
    int m = idx >> 14;
    int rem = idx & 16383;
    int k = rem >> 7;
    int n = rem & 127;
    float v = w[(size_t)m * 16384 + k * 128 + n];
    __nv_bfloat16 h = __float2bfloat16_rn(v);
    float res = v - __bfloat162float(h);
    __nv_bfloat16 l = __float2bfloat16_rn(res);
    size_t dst = (size_t)m * 16384 + n * 128 + k;
    hi[dst] = h;
    lo[dst] = l;
}

// ---------------- mma helpers ----------------
__device__ __forceinline__ void mma16816(float* c, uint32_t a0, uint32_t a1,
                                         uint32_t a2, uint32_t a3,
                                         uint32_t b0, uint32_t b1) {
    asm volatile(
        "mma.sync.aligned.m16n8k16.row.col.f32.bf16.bf16.f32 "
        "{%0,%1,%2,%3}, {%4,%5,%6,%7}, {%8,%9}, {%0,%1,%2,%3};"
        : "+f"(c[0]), "+f"(c[1]), "+f"(c[2]), "+f"(c[3])
        : "r"(a0), "r"(a1), "r"(a2), "r"(a3), "r"(b0), "r"(b1));
}

__device__ __forceinline__ uint32_t pack_bf2(__nv_bfloat16 a, __nv_bfloat16 b) {
    __nv_bfloat162 t;
    t.x = a; t.y = b;
    return *reinterpret_cast<uint32_t*>(&t);
}

__device__ __forceinline__ void red_v4(float* ptr, float x, float y, float z, float w) {
    asm volatile("red.global.add.v4.f32 [%0], {%1,%2,%3,%4};"
                 :: "l"(ptr), "f"(x), "f"(y), "f"(z), "f"(w) : "memory");
}

// ---------------- fused GEMM kernel ----------------
// ROOTMODE=1: out[rowBase+e] = (relu?)h[rowBase+e] @ W + bias   (coalesced store)
// ROOTMODE=0: out[dst[e]]   += ((relu?)h[src[e]] @ W[rel]) * invc[rel,dst]  (red.v4)
template<int ROOTMODE, int RELU>
__global__ void __launch_bounds__(512, 1)
k_mma(const float* __restrict__ h,
      const __nv_bfloat16* __restrict__ Whi,
      const __nv_bfloat16* __restrict__ Wlo,
      const float* __restrict__ bias,
      const int* __restrict__ src,
      const int* __restrict__ dst,
      float* __restrict__ out) {
    extern __shared__ uint32_t sm[];
    uint32_t* sAhi = sm + SM_AHI;
    uint32_t* sAlo = sm + SM_ALO;
    uint32_t* sWhi = sm + SM_WHI;
    uint32_t* sWlo = sm + SM_WLO;
    int*   sDst  = (int*)(sm + SM_DST);
    float* sInv  = (float*)(sm + SM_INV);
    float* sBias = (float*)(sm + SM_BIAS);
    int*   sSrc  = (int*)(sm + SM_SRC);
    float* sOut  = (float*)(sm + SM_AHI);   // reused after MMA phase (128*OSTR fp32)

    int t = blockIdx.x;
    int cnt, r = 0, off = 0, rowBase = 0;
    if (ROOTMODE) {
        rowBase = t * TILE_E;
        cnt = N_NODES - rowBase;
        if (cnt > TILE_E) cnt = TILE_E;
    } else {
        cnt = g_tileCnt[t];
        if (cnt == 0) return;
        r = g_tileRel[t];
        off = g_tileOff[t];
    }

    const __nv_bfloat16* gwh = Whi + (size_t)r * (D * D);
    const __nv_bfloat16* gwl = Wlo + (size_t)r * (D * D);

    // ---- W staging (hi+lo), [n][k] rows of 128 bf16 -> smem stride 68 words
    for (int i = threadIdx.x; i < 128 * 16; i += 512) {
        int n = i >> 4, q = i & 15;
        *(uint4*)&sWhi[n * 68 + q * 4] = *(const uint4*)(gwh + n * 128 + q * 8);
        *(uint4*)&sWlo[n * 68 + q * 4] = *(const uint4*)(gwl + n * 128 + q * 8);
    }
    // ---- indices / bias
    if (threadIdx.x < TILE_E) {
        int i = threadIdx.x;
        if (ROOTMODE) {
            sBias[i] = bias[i];
        } else {
            if (i < cnt) {
                int e = g_perm[off + i];
                sSrc[i] = src[e];
                int d = dst[e];
                sDst[i] = d;
                sInv[i] = g_invc[(size_t)r * N_NODES + d];
            } else {
                sSrc[i] = 0; sDst[i] = 0; sInv[i] = 0.f;
            }
        }
    }
    __syncthreads();

    // ---- A staging: gather rows, relu, split to bf16 hi/lo
    for (int i = threadIdx.x; i < 128 * 32; i += 512) {
        int e = i >> 5, q = i & 31;
        float4 v = make_float4(0.f, 0.f, 0.f, 0.f);
        if (e < cnt) {
            const float* hp = ROOTMODE ? (h + (size_t)(rowBase + e) * D)
                                       : (h + (size_t)sSrc[e] * D);
            v = *(const float4*)(hp + q * 4);
            if (RELU) {
                v.x = fmaxf(v.x, 0.f); v.y = fmaxf(v.y, 0.f);
                v.z = fmaxf(v.z, 0.f); v.w = fmaxf(v.w, 0.f);
            }
        }
        __nv_bfloat16 h0 = __float2bfloat16_rn(v.x), h1 = __float2bfloat16_rn(v.y);
        __nv_bfloat16 h2 = __float2bfloat16_rn(v.z), h3 = __float2bfloat16_rn(v.w);
        __nv_bfloat16 l0 = __float2bfloat16_rn(v.x - __bfloat162float(h0));
        __nv_bfloat16 l1 = __float2bfloat16_rn(v.y - __bfloat162float(h1));
        __nv_bfloat16 l2 = __float2bfloat16_rn(v.z - __bfloat162float(h2));
        __nv_bfloat16 l3 = __float2bfloat16_rn(v.w - __bfloat162float(h3));
        int base = e * 68 + q * 2;
        uint2 hw, lw;
        hw.x = pack_bf2(h0, h1); hw.y = pack_bf2(h2, h3);
        lw.x = pack_bf2(l0, l1); lw.y = pack_bf2(l2, l3);
        *(uint2*)&sAhi[base] = hw;
        *(uint2*)&sAlo[base] = lw;
    }
    __syncthreads();

    // ---- MMA phase: 16 warps = 8 m-tiles (16 rows) x 2 n-halves (64 cols)
    int lane = threadIdx.x & 31;
    int wid  = threadIdx.x >> 5;
    int g    = lane >> 2;     // 0..7
    int tig  = lane & 3;      // 0..3
    int mtile = wid & 7;
    int nhalf = wid >> 3;
    int m0 = mtile * 16;

    float acc[8][4];
#pragma unroll
    for (int j = 0; j < 8; j++)
#pragma unroll
        for (int c = 0; c < 4; c++) acc[j][c] = 0.f;

    int aBase = (m0 + g) * 68 + tig;
    int bBase = (nhalf * 64 + g) * 68 + tig;

#pragma unroll
    for (int kc = 0; kc < 8; kc++) {
        int ko = kc * 8;
        uint32_t ah0 = sAhi[aBase + ko];
        uint32_t ah1 = sAhi[aBase + 544 + ko];
        uint32_t ah2 = sAhi[aBase + ko + 4];
        uint32_t ah3 = sAhi[aBase + 544 + ko + 4];
        uint32_t al0 = sAlo[aBase + ko];
        uint32_t al1 = sAlo[aBase + 544 + ko];
        uint32_t al2 = sAlo[aBase + ko + 4];
        uint32_t al3 = sAlo[aBase + 544 + ko + 4];
#pragma unroll
        for (int j = 0; j < 8; j++) {
            int bo = bBase + j * 544 + ko;
            uint32_t bh0 = sWhi[bo], bh1 = sWhi[bo + 4];
            uint32_t bl0 = sWlo[bo], bl1 = sWlo[bo + 4];
            mma16816(acc[j], al0, al1, al2, al3, bh0, bh1);  // lo*hi
            mma16816(acc[j], ah0, ah1, ah2, ah3, bl0, bl1);  // hi*lo
            mma16816(acc[j], ah0, ah1, ah2, ah3, bh0, bh1);  // hi*hi
        }
    }

    // ---- epilogue: bounce through smem, then coalesced v4 stores / reductions
    __syncthreads();   // all smem A reads done; safe to reuse region as sOut

    int colb = nhalf * 64 + tig * 2;
    int lr0 = m0 + g, lr1 = lr0 + 8;
#pragma unroll
    for (int j = 0; j < 8; j++) {
        int col = colb + j * 8;
        sOut[lr0 * OSTR + col]     = acc[j][0];
        sOut[lr0 * OSTR + col + 1] = acc[j][1];
        sOut[lr1 * OSTR + col]     = acc[j][2];
        sOut[lr1 * OSTR + col + 1] = acc[j][3];
    }
    __syncthreads();

    if (ROOTMODE) {
        for (int i = threadIdx.x; i < 128 * 32; i += 512) {
            int e = i >> 5, q = i & 31;
            int row = rowBase + e;
            if (row < N_NODES) {
                float4 v = *(const float4*)&sOut[e * OSTR + q * 4];
                v.x += sBias[q * 4];
                v.y += sBias[q * 4 + 1];
                v.z += sBias[q * 4 + 2];
                v.w += sBias[q * 4 + 3];
                *(float4*)(out + (size_t)row * D + q * 4) = v;
            }
        }
    } else {
        for (int i = threadIdx.x; i < 128 * 32; i += 512) {
            int e = i >> 5, q = i & 31;
            if (e < cnt) {
                float inv = sInv[e];
                float4 v = *(const float4*)&sOut[e * OSTR + q * 4];
                float* op = out + (size_t)sDst[e] * D + q * 4;
                red_v4(op, v.x * inv, v.y * inv, v.z * inv, v.w * inv);
            }
        }
    }
}

// ---------------- launch ----------------
extern "C" void kernel_launch(void* const* d_in, const int* in_sizes, int n_in,
                              void* d_out, int out_size) {
    const int*   x     = (const int*)d_in[0];
    const int*   edge  = (const int*)d_in[1];   // [2,E]: src row then dst row
    const int*   etype = (const int*)d_in[2];
    const float* emb   = (const float*)d_in[3];
    const float* w1    = (const float*)d_in[4];
    const float* root1 = (const float*)d_in[5];
    const float* b1    = (const float*)d_in[6];
    const float* w2    = (const float*)d_in[7];
    const float* root2 = (const float*)d_in[8];
    const float* b2    = (const float*)d_in[9];
    float* out = (float*)d_out;

    const int* src  = edge;
    const int* dstp = edge + E_EDGES;

    cudaFuncSetAttribute(k_mma<0, 0>, cudaFuncAttributeMaxDynamicSharedMemorySize, SMEM_BYTES);
    cudaFuncSetAttribute(k_mma<0, 1>, cudaFuncAttributeMaxDynamicSharedMemorySize, SMEM_BYTES);
    cudaFuncSetAttribute(k_mma<1, 0>, cudaFuncAttributeMaxDynamicSharedMemorySize, SMEM_BYTES);
    cudaFuncSetAttribute(k_mma<1, 1>, cudaFuncAttributeMaxDynamicSharedMemorySize, SMEM_BYTES);

    float *h0, *buf;
    __nv_bfloat16 *w1hi, *w1lo, *w2hi, *w2lo, *r1hi, *r1lo, *r2hi, *r2lo;
    {
        void* p;
        cudaGetSymbolAddress(&p, g_h0);   h0   = (float*)p;
        cudaGetSymbolAddress(&p, g_buf);  buf  = (float*)p;
        cudaGetSymbolAddress(&p, g_w1hi); w1hi = (__nv_bfloat16*)p;
        cudaGetSymbolAddress(&p, g_w1lo); w1lo = (__nv_bfloat16*)p;
        cudaGetSymbolAddress(&p, g_w2hi); w2hi = (__nv_bfloat16*)p;
        cudaGetSymbolAddress(&p, g_w2lo); w2lo = (__nv_bfloat16*)p;
        cudaGetSymbolAddress(&p, g_r1hi); r1hi = (__nv_bfloat16*)p;
        cudaGetSymbolAddress(&p, g_r1lo); r1lo = (__nv_bfloat16*)p;
        cudaGetSymbolAddress(&p, g_r2hi); r2hi = (__nv_bfloat16*)p;
        cudaGetSymbolAddress(&p, g_r2lo); r2lo = (__nv_bfloat16*)p;
    }

    // ---- preprocessing
    k_zero_counts<<<(RELS * N_NODES + 255) / 256, 256>>>();
    k_count<<<(E_EDGES + 255) / 256, 256>>>(etype, dstp);
    k_inv<<<(RELS * N_NODES + 255) / 256, 256>>>();
    k_scan<<<1, 1>>>();
    k_scatter<<<(E_EDGES + 255) / 256, 256>>>(etype);
    k_tiles<<<1, 256>>>();
    k_gather_emb<<<(N_NODES * D + 255) / 256, 256>>>(x, emb);

    // ---- weight split + transpose (bf16 hi/lo, [n][k])
    int wt = RELS * D * D;
    k_wsplit<<<(wt + 255) / 256, 256>>>(w1, w1hi, w1lo, wt);
    k_wsplit<<<(wt + 255) / 256, 256>>>(w2, w2hi, w2lo, wt);
    k_wsplit<<<(D * D + 255) / 256, 256>>>(root1, r1hi, r1lo, D * D);
    k_wsplit<<<(D * D + 255) / 256, 256>>>(root2, r2hi, r2lo, D * D);

    // ---- layer 1: buf = h0@root1 + b1 ; buf += edge messages
    k_mma<1, 0><<<ROOT_TILES, 512, SMEM_BYTES>>>(h0, r1hi, r1lo, b1, src, dstp, buf);
    k_mma<0, 0><<<MAX_TILES, 512, SMEM_BYTES>>>(h0, w1hi, w1lo, b1, src, dstp, buf);

    // ---- layer 2: relu fused into reads of buf
    k_mma<1, 1><<<ROOT_TILES, 512, SMEM_BYTES>>>(buf, r2hi, r2lo, b2, src, dstp, out);
    k_mma<0, 1><<<MAX_TILES, 512, SMEM_BYTES>>>(buf, w2hi, w2lo, b2, src, dstp, out);
}